// round 9
// baseline (speedup 1.0000x reference)
#include <cuda_runtime.h>
#include <cstdint>
#include <cstddef>

#define BB 16
#define SS 40
#define HIDD 256
#define G4 1024

// ---------------- static device scratch (no runtime allocs) ----------------
__device__ float g_X[(size_t)SS * G4 * BB];        // [t][j][b]
__device__ float g_h[2][HIDD * BB];                // ping-pong hidden state [j][b]
__device__ float g_instr[HIDD * BB];               // [j][b]
__device__ float g_f1[(size_t)BB * 256 * 1024];    // [b][r*1024+c]
__device__ unsigned g_cnt = 0;                     // barrier arrivals (self-resetting)
__device__ unsigned g_gen = 0;                     // barrier generation (monotonic)

__device__ __forceinline__ float2 ffma2(float2 a, float2 b, float2 c) {
    union U { float2 f; unsigned long long u; };
    U A, B, C, D;
    A.f = a; B.f = b; C.f = c;
    asm("fma.rn.f32x2 %0, %1, %2, %3;" : "=l"(D.u) : "l"(A.u), "l"(B.u), "l"(C.u));
    return D.f;
}

// ========== Kernel A: g_X[t][j][b] = emb[idx[b,t]] . w_ih[j] + b_ih[j] + b_hh[j] ==========
__global__ void __launch_bounds__(256) kA(const float* __restrict__ emb,
                                          const int* __restrict__ idx,
                                          const float* __restrict__ w_ih,
                                          const float* __restrict__ b_ih,
                                          const float* __restrict__ b_hh) {
    __shared__ float esm[256 * 18];   // [k][b], stride 18 (pad)
    __shared__ int idxs[16];
    int jc = blockIdx.x, t = blockIdx.y, tid = threadIdx.x;
    if (tid < 16) idxs[tid] = idx[tid * SS + t];
    __syncthreads();
    for (int e = tid; e < 4096; e += 256) {
        int b = e >> 8, k = e & 255;
        esm[k * 18 + b] = emb[(size_t)idxs[b] * 256 + k];
    }
    __syncthreads();
    int j = jc * 256 + tid;
    float bias = b_ih[j] + b_hh[j];
    float2 acc[8];
#pragma unroll
    for (int p = 0; p < 8; p++) acc[p] = make_float2(bias, bias);
    const float4* wr = reinterpret_cast<const float4*>(w_ih) + (size_t)j * 64;
    const float2* es2 = reinterpret_cast<const float2*>(esm);
#pragma unroll 4
    for (int k4 = 0; k4 < 64; k4++) {
        float4 w4 = wr[k4];
        float wv[4] = {w4.x, w4.y, w4.z, w4.w};
#pragma unroll
        for (int kk = 0; kk < 4; kk++) {
            int k = k4 * 4 + kk;
            float2 wd = make_float2(wv[kk], wv[kk]);
            const float2* hp = es2 + k * 9;
#pragma unroll
            for (int p = 0; p < 8; p++) acc[p] = ffma2(wd, hp[p], acc[p]);
        }
    }
    float2* xo = reinterpret_cast<float2*>(g_X + ((size_t)t * G4 + j) * BB);
#pragma unroll
    for (int p = 0; p < 8; p++) xo[p] = acc[p];
}

// ========== Kernel B: persistent LSTM recurrence, 16 blocks + global sense barrier ==========
// Block bk owns hid units [bk*16, bk*16+16) -> 64 gate rows (i/f/g/o x 16).
__global__ void __launch_bounds__(256) kB(const float* __restrict__ w_hh,
                                          const int* __restrict__ len) {
    extern __shared__ float sm[];
    float2* wd2 = reinterpret_cast<float2*>(sm);   // [256 k][64 r] duplicated pairs (128KB)
    float*  hsm = sm + 32768;                      // [256 k][16 b] (16KB)
    float*  gsm = hsm + HIDD * BB;                 // [64 r][16 b]  (4KB)
    float*  cs  = gsm + 64 * BB;                   // [256]         (1KB)
    int bk = blockIdx.x, tid = threadIdx.x;

    for (int e = tid; e < 16384; e += 256) {       // fill weight slice (coalesced on k)
        int r = e >> 8, k = e & 255;
        int jgr = (r >> 4) * 256 + bk * 16 + (r & 15);
        float w = w_hh[(size_t)jgr * 256 + k];
        wd2[k * 64 + r] = make_float2(w, w);
    }
    cs[tid] = 0.f;

    int r = tid >> 2, bq = tid & 3;                // compute mapping: 64 rows x 4 b-quads
    int jg = (r >> 4) * 256 + bk * 16 + (r & 15);
    int hl = tid >> 4, b = tid & 15;               // epilogue mapping
    int lb = len[b];
    const float2* hsm2 = reinterpret_cast<const float2*>(hsm);

    for (int t = 0; t < SS; t++) {
        if (t > 0) {
            const float* src = g_h[t & 1];
            for (int e = tid; e < HIDD * BB; e += 256) hsm[e] = src[e];
        }
        __syncthreads();
        const float* Xs = g_X + (size_t)t * G4 * BB;
        float2 a0 = *reinterpret_cast<const float2*>(Xs + jg * 16 + bq * 4);
        float2 a1 = *reinterpret_cast<const float2*>(Xs + jg * 16 + bq * 4 + 2);
        if (t > 0) {
#pragma unroll 8
            for (int k = 0; k < 256; k++) {
                float2 w2 = wd2[k * 64 + r];
                a0 = ffma2(w2, hsm2[k * 8 + bq * 2], a0);
                a1 = ffma2(w2, hsm2[k * 8 + bq * 2 + 1], a1);
            }
        }
        *reinterpret_cast<float2*>(gsm + r * 16 + bq * 4) = a0;
        *reinterpret_cast<float2*>(gsm + r * 16 + bq * 4 + 2) = a1;
        __syncthreads();
        {
            float gi = gsm[hl * 16 + b];
            float gf = gsm[(16 + hl) * 16 + b];
            float gg = gsm[(32 + hl) * 16 + b];
            float go = gsm[(48 + hl) * 16 + b];
            float si = 1.f / (1.f + expf(-gi));
            float sf = 1.f / (1.f + expf(-gf));
            float tg = tanhf(gg);
            float so = 1.f / (1.f + expf(-go));
            float cn = sf * cs[tid] + si * tg;
            float hn = so * tanhf(cn);
            bool mk = (t < lb);
            float hold = (t == 0) ? 0.f : hsm[(bk * 16 + hl) * 16 + b];
            if (mk) cs[tid] = cn;
            g_h[(t + 1) & 1][(bk * 16 + hl) * 16 + b] = mk ? hn : hold;
        }
        if (t < SS - 1) {
            __syncthreads();
            if (tid == 0) {
                __threadfence();
                unsigned mygen = *(volatile unsigned*)&g_gen;
                unsigned old = atomicAdd(&g_cnt, 1u);
                if (old == 15u) {
                    atomicExch(&g_cnt, 0u);   // reset BEFORE release so replays stay clean
                    __threadfence();
                    atomicAdd(&g_gen, 1u);
                } else {
                    while (*(volatile unsigned*)&g_gen == mygen) { }
                }
                __threadfence();
            }
            __syncthreads();
        }
    }
}

// ========== Kernel C: instr[j][b] = tanh(h_final[:,b] . e2d_w[j] + e2d_b[j]) ==========
__global__ void __launch_bounds__(256) kC(const float* __restrict__ e2d_w,
                                          const float* __restrict__ e2d_b) {
    __shared__ float hb[256];
    int b = blockIdx.x, j = threadIdx.x;
    hb[j] = g_h[0][j * 16 + b];      // 40 steps -> final state lands in buffer 0
    __syncthreads();
    float acc = e2d_b[j];
    const float4* wr = reinterpret_cast<const float4*>(e2d_w) + (size_t)j * 64;
#pragma unroll 8
    for (int k4 = 0; k4 < 64; k4++) {
        float4 w = wr[k4];
        acc += w.x * hb[k4 * 4] + w.y * hb[k4 * 4 + 1] + w.z * hb[k4 * 4 + 2] + w.w * hb[k4 * 4 + 3];
    }
    g_instr[j * 16 + b] = tanhf(acc);
}

// ========== Kernel D: f1[b][m] = leaky_relu(instr[b] . lin1_w[m] + lin1_b[m]) ==========
// 64 weight rows staged per block; thread = (row, 4-batch quad). DRAM streaming bound.
__global__ void __launch_bounds__(256) kD(const float* __restrict__ lin1_w,
                                          const float* __restrict__ lin1_b) {
    extern __shared__ float sm[];
    float* ws = sm;                  // [64 m][256 k], row stride 260 (16B-aligned, pad)
    float* is = sm + 64 * 260;       // [256 k][16 b], stride 18
    int tid = threadIdx.x;
    size_t mb = (size_t)blockIdx.x * 64;
    for (int e = tid; e < 4096; e += 256) is[(e >> 4) * 18 + (e & 15)] = g_instr[e];
    const float4* lw4 = reinterpret_cast<const float4*>(lin1_w);
#pragma unroll
    for (int i = 0; i < 16; i++) {
        int f = tid + 256 * i;
        int ml = f >> 6, kw = f & 63;
        float4 v = lw4[(mb + ml) * 64 + kw];
        *reinterpret_cast<float4*>(ws + ml * 260 + kw * 4) = v;
    }
    __syncthreads();
    int ml = tid >> 2, bg = tid & 3;
    float bias = lin1_b[mb + ml];
    float2 a0 = make_float2(bias, bias), a1 = a0;
    const float2* is2 = reinterpret_cast<const float2*>(is);
    const float4* wsr = reinterpret_cast<const float4*>(ws + ml * 260);
#pragma unroll 4
    for (int kq = 0; kq < 64; kq++) {
        float4 w4 = wsr[kq];
        float wv[4] = {w4.x, w4.y, w4.z, w4.w};
#pragma unroll
        for (int kk = 0; kk < 4; kk++) {
            int k = kq * 4 + kk;
            float2 wd = make_float2(wv[kk], wv[kk]);
            a0 = ffma2(wd, is2[k * 9 + bg * 2], a0);
            a1 = ffma2(wd, is2[k * 9 + bg * 2 + 1], a1);
        }
    }
    float vals[4] = {a0.x, a0.y, a1.x, a1.y};
    size_t m = mb + ml;
#pragma unroll
    for (int q = 0; q < 4; q++) {
        float v = vals[q];
        v = (v >= 0.f) ? v : 0.01f * v;
        g_f1[(size_t)(bg * 4 + q) * 262144 + m] = v;
    }
}

// ========== Kernel E: out[b][p] = clip(max_r(relu(sum_c feat[b,c,p]*f1[b,r,c])*sc[r]+of[r]),0,1) ==========
__global__ void __launch_bounds__(256) kE(const float* __restrict__ feat,
                                          const float* __restrict__ gam,
                                          const float* __restrict__ bet,
                                          const float* __restrict__ mea,
                                          const float* __restrict__ var,
                                          float* __restrict__ out) {
    __shared__ float fs[16 * 260];   // f1 chunk transposed [cc][r], stride 260
    __shared__ float fe[16 * 68];    // feature chunk [cc][p], stride 68
    __shared__ float red[32 * 64];   // max-reduction [tr][p]
    int pt = blockIdx.x, b = blockIdx.y, tid = threadIdx.x;
    int tr = tid >> 3, tp = tid & 7;
    int r0 = tr * 8, p0 = tp * 8;
    float2 acc[8][4];
#pragma unroll
    for (int i = 0; i < 8; i++)
#pragma unroll
        for (int j = 0; j < 4; j++) acc[i][j] = make_float2(0.f, 0.f);
    const float* f1b = g_f1 + (size_t)b * 262144;
    const float* ftb = feat + (size_t)b * 1048576 + pt * 64;
    int sr = tid >> 2, cq = tid & 3;
    int scc = tid >> 4, spq = tid & 15;
    for (int ch = 0; ch < 64; ch++) {
        int c0 = ch * 16;
        __syncthreads();
#pragma unroll
        for (int i = 0; i < 4; i++) {
            int r = sr + 64 * i;
            float4 v = *reinterpret_cast<const float4*>(f1b + (size_t)r * 1024 + c0 + cq * 4);
            fs[(cq * 4 + 0) * 260 + r] = v.x;
            fs[(cq * 4 + 1) * 260 + r] = v.y;
            fs[(cq * 4 + 2) * 260 + r] = v.z;
            fs[(cq * 4 + 3) * 260 + r] = v.w;
        }
        {
            float4 u = *reinterpret_cast<const float4*>(ftb + (size_t)(c0 + scc) * 1024 + spq * 4);
            *reinterpret_cast<float4*>(fe + scc * 68 + spq * 4) = u;
        }
        __syncthreads();
#pragma unroll 2
        for (int cc = 0; cc < 16; cc++) {
            float4 fa = *reinterpret_cast<const float4*>(fs + cc * 260 + r0);
            float4 fb = *reinterpret_cast<const float4*>(fs + cc * 260 + r0 + 4);
            float fr[8] = {fa.x, fa.y, fa.z, fa.w, fb.x, fb.y, fb.z, fb.w};
            float4 e0 = *reinterpret_cast<const float4*>(fe + cc * 68 + p0);
            float4 e1 = *reinterpret_cast<const float4*>(fe + cc * 68 + p0 + 4);
            float2 fp[4] = {make_float2(e0.x, e0.y), make_float2(e0.z, e0.w),
                            make_float2(e1.x, e1.y), make_float2(e1.z, e1.w)};
#pragma unroll
            for (int rr = 0; rr < 8; rr++) {
                float2 wd = make_float2(fr[rr], fr[rr]);
#pragma unroll
                for (int pp = 0; pp < 4; pp++) acc[rr][pp] = ffma2(wd, fp[pp], acc[rr][pp]);
            }
        }
    }
    float pm[8];
#pragma unroll
    for (int i = 0; i < 8; i++) pm[i] = -1e30f;
#pragma unroll
    for (int rr = 0; rr < 8; rr++) {
        int rg = r0 + rr;
        float sc = gam[rg] * rsqrtf(var[rg] + 1e-5f);
        float of = bet[rg] - mea[rg] * sc;
#pragma unroll
        for (int pp = 0; pp < 4; pp++) {
            float vx = fmaxf(acc[rr][pp].x, 0.f) * sc + of;
            float vy = fmaxf(acc[rr][pp].y, 0.f) * sc + of;
            pm[pp * 2]     = fmaxf(pm[pp * 2], vx);
            pm[pp * 2 + 1] = fmaxf(pm[pp * 2 + 1], vy);
        }
    }
#pragma unroll
    for (int i = 0; i < 8; i++) red[tr * 64 + p0 + i] = pm[i];
    __syncthreads();
    if (tid < 64) {
        float m = red[tid];
#pragma unroll
        for (int w = 1; w < 32; w++) m = fmaxf(m, red[w * 64 + tid]);
        m = fminf(fmaxf(m, 0.f), 1.f);
        out[(size_t)b * 1024 + pt * 64 + tid] = m;
    }
}

#define SMEM_B_BYTES ((32768 + 4096 + 1024 + 256) * 4)
#define SMEM_D_BYTES ((64 * 260 + 256 * 18) * 4)

extern "C" void kernel_launch(void* const* d_in, const int* in_sizes, int n_in,
                              void* d_out, int out_size) {
    const float* feature = (const float*)d_in[0];
    // d_in[1] depth: unused. d_in[4] only_train_rele: unused.
    const int*   idx     = (const int*)d_in[2];
    const int*   len     = (const int*)d_in[3];
    const float* emb     = (const float*)d_in[5];
    const float* w_ih    = (const float*)d_in[6];
    const float* w_hh    = (const float*)d_in[7];
    const float* b_ih    = (const float*)d_in[8];
    const float* b_hh    = (const float*)d_in[9];
    const float* e2d_w   = (const float*)d_in[10];
    const float* e2d_b   = (const float*)d_in[11];
    const float* lin1_w  = (const float*)d_in[12];
    const float* lin1_b  = (const float*)d_in[13];
    const float* gam     = (const float*)d_in[14];
    const float* bet     = (const float*)d_in[15];
    const float* mea     = (const float*)d_in[16];
    const float* var     = (const float*)d_in[17];
    float* out = (float*)d_out;

    cudaFuncSetAttribute(kB, cudaFuncAttributeMaxDynamicSharedMemorySize, SMEM_B_BYTES);
    cudaFuncSetAttribute(kD, cudaFuncAttributeMaxDynamicSharedMemorySize, SMEM_D_BYTES);

    kA<<<dim3(4, 40), 256>>>(emb, idx, w_ih, b_ih, b_hh);
    kB<<<16, 256, SMEM_B_BYTES>>>(w_hh, len);
    kC<<<16, 256>>>(e2d_w, e2d_b);
    kD<<<4096, 256, SMEM_D_BYTES>>>(lin1_w, lin1_b);
    kE<<<dim3(16, 16), 256>>>(feature, gam, bet, mea, var, out);
}